// round 3
// baseline (speedup 1.0000x reference)
#include <cuda_runtime.h>

#define NN 100000
#define EE 1600000
// H = 64, hidden = 128, O = 64

// Scratch (device globals — no allocation allowed)
__device__ float g_agg1[NN * 64];    // layer1 neighbor sums   (25.6 MB)
__device__ float g_h   [NN * 128];   // layer1 output (post-ReLU, 51.2 MB)
__device__ float g_t   [NN * 64];    // h @ W2_l^T (transform-then-aggregate)
__device__ float g_agg2[NN * 64];    // layer2 neighbor sums
__device__ float g_cnt [NN];         // in-degree counts (fp32)

// ---------------------------------------------------------------------------
// Zero all accumulators (grid-stride, float4 stores)
// ---------------------------------------------------------------------------
__global__ void zero_kernel() {
    const int i = blockIdx.x * blockDim.x + threadIdx.x;
    const int stride = gridDim.x * blockDim.x;
    const float4 z = make_float4(0.f, 0.f, 0.f, 0.f);
    for (int j = i; j < NN * 16; j += stride) {           // NN*64 floats / 4
        reinterpret_cast<float4*>(g_agg1)[j] = z;
        reinterpret_cast<float4*>(g_agg2)[j] = z;
    }
    for (int j = i; j < NN / 4; j += stride)
        reinterpret_cast<float4*>(g_cnt)[j] = z;
}

// ---------------------------------------------------------------------------
// Edge scatter: 16 threads per edge, each handles one float4 (4 channels).
// LAYER==1: feat = x (arg), agg = g_agg1, also counts degrees (lane c==0).
// LAYER==2: feat = g_t,     agg = g_agg2.
// ---------------------------------------------------------------------------
template <int LAYER>
__global__ void __launch_bounds__(256) scatter64_kernel(
    const float* __restrict__ x,
    const int* __restrict__ src,
    const int* __restrict__ dst)
{
    const int idx = blockIdx.x * 256 + threadIdx.x;
    const int e = idx >> 4;
    const int c = idx & 15;
    if (e >= EE) return;

    const int s = __ldg(src + e);
    const int d = __ldg(dst + e);

    const float* feat = (LAYER == 1) ? x : g_t;
    float*       agg  = (LAYER == 1) ? g_agg1 : g_agg2;

    const float4 v = __ldg(
        reinterpret_cast<const float4*>(feat + (size_t)s * 64) + c);
    float* p = agg + (size_t)d * 64 + c * 4;
    asm volatile("red.global.add.v4.f32 [%0], {%1,%2,%3,%4};"
                 :: "l"(p), "f"(v.x), "f"(v.y), "f"(v.z), "f"(v.w)
                 : "memory");

    if (LAYER == 1 && c == 0) {
        float* cp = g_cnt + d;
        asm volatile("red.global.add.f32 [%0], %1;"
                     :: "l"(cp), "f"(1.0f) : "memory");
    }
}

// ---------------------------------------------------------------------------
// Layer 1 dense: h = relu( (agg1/cnt) @ W1_l^T + b1_l + x @ W1_r^T )
// One node per 128-thread block; thread t computes output channel t.
// ---------------------------------------------------------------------------
__global__ void __launch_bounds__(128) layer1_kernel(
    const float* __restrict__ x,
    const float* __restrict__ W1l,   // [128,64] row-major
    const float* __restrict__ b1l,   // [128]
    const float* __restrict__ W1r)   // [128,64]
{
    __shared__ float sm[128];        // [0:64) mean row, [64:128) x row
    const int node = blockIdx.x;
    const int t = threadIdx.x;

    if (t < 64) {
        const float inv = 1.0f / fmaxf(g_cnt[node], 1.0f);
        sm[t] = g_agg1[(size_t)node * 64 + t] * inv;
    } else {
        sm[t] = x[(size_t)node * 64 + (t - 64)];
    }
    __syncthreads();

    const float4* wl4 = reinterpret_cast<const float4*>(W1l + t * 64);
    const float4* wr4 = reinterpret_cast<const float4*>(W1r + t * 64);
    const float4* m4  = reinterpret_cast<const float4*>(sm);
    const float4* x4  = reinterpret_cast<const float4*>(sm + 64);

    float acc = b1l[t];
#pragma unroll
    for (int k = 0; k < 16; k++) {
        const float4 a = wl4[k];
        const float4 m = m4[k];
        acc += a.x * m.x + a.y * m.y + a.z * m.z + a.w * m.w;
        const float4 b  = wr4[k];
        const float4 xv = x4[k];
        acc += b.x * xv.x + b.y * xv.y + b.z * xv.z + b.w * xv.w;
    }
    g_h[(size_t)node * 128 + t] = fmaxf(acc, 0.0f);
}

// ---------------------------------------------------------------------------
// Layer 2 transforms: t = h @ W2_l^T  (threads 0..63)
//                     out_partial = h @ W2_r^T + b2_l  (threads 64..127)
// ---------------------------------------------------------------------------
__global__ void __launch_bounds__(128) layer2t_kernel(
    const float* __restrict__ W2l,   // [64,128]
    const float* __restrict__ b2l,   // [64]
    const float* __restrict__ W2r,   // [64,128]
    float* __restrict__ out)
{
    __shared__ float sm[128];
    const int node = blockIdx.x;
    const int t = threadIdx.x;

    sm[t] = g_h[(size_t)node * 128 + t];
    __syncthreads();

    const bool is_l = (t < 64);
    const int c = is_l ? t : (t - 64);
    const float* W = (is_l ? W2l : W2r) + c * 128;
    const float4* w4 = reinterpret_cast<const float4*>(W);
    const float4* h4 = reinterpret_cast<const float4*>(sm);

    float acc = is_l ? 0.0f : b2l[c];
#pragma unroll
    for (int k = 0; k < 32; k++) {
        const float4 w = w4[k];
        const float4 h = h4[k];
        acc += w.x * h.x + w.y * h.y + w.z * h.z + w.w * h.w;
    }
    if (is_l) g_t[(size_t)node * 64 + c] = acc;
    else      out[(size_t)node * 64 + c] = acc;
}

// ---------------------------------------------------------------------------
// Finalize: out += agg2 / clip(cnt,1)
// ---------------------------------------------------------------------------
__global__ void __launch_bounds__(256) finalize_kernel(float* __restrict__ out)
{
    const int idx = blockIdx.x * 256 + threadIdx.x;   // one float4 each
    if (idx >= NN * 16) return;
    const int node = idx >> 4;
    const float inv = 1.0f / fmaxf(g_cnt[node], 1.0f);
    const float4 a = reinterpret_cast<const float4*>(g_agg2)[idx];
    float4* o = reinterpret_cast<float4*>(out) + idx;
    float4 v = *o;
    v.x += a.x * inv;
    v.y += a.y * inv;
    v.z += a.z * inv;
    v.w += a.w * inv;
    *o = v;
}

// ---------------------------------------------------------------------------
extern "C" void kernel_launch(void* const* d_in, const int* in_sizes, int n_in,
                              void* d_out, int out_size)
{
    const float* x    = (const float*)d_in[0];
    const int*   ei   = (const int*)  d_in[1];
    const float* W1l  = (const float*)d_in[2];
    const float* b1l  = (const float*)d_in[3];
    const float* W1r  = (const float*)d_in[4];
    const float* W2l  = (const float*)d_in[5];
    const float* b2l  = (const float*)d_in[6];
    const float* W2r  = (const float*)d_in[7];
    float* out = (float*)d_out;

    const int* src = ei;
    const int* dst = ei + EE;

    zero_kernel<<<4096, 256>>>();

    // Layer 1 aggregation (+ degree count)
    scatter64_kernel<1><<<(EE * 16) / 256, 256>>>(x, src, dst);

    // Layer 1 dense + ReLU
    layer1_kernel<<<NN, 128>>>(x, W1l, b1l, W1r);

    // Layer 2: transform first (halves aggregation channels)
    layer2t_kernel<<<NN, 128>>>(W2l, b2l, W2r, out);

    // Layer 2 aggregation of transformed features
    scatter64_kernel<2><<<(EE * 16) / 256, 256>>>(x, src, dst);

    // out += mean-aggregated transformed neighbors
    finalize_kernel<<<(NN * 16 + 255) / 256, 256>>>(out);
}

// round 9
// speedup vs baseline: 6.9367x; 6.9367x over previous
#include <cuda_runtime.h>

#define NN 100000
#define EE 1600000
// H = 64, hidden = 128, O = 64

// Scratch (device globals — no allocation allowed)
__device__ float g_agg1[NN * 64];    // layer1 neighbor sums   (25.6 MB)
__device__ float g_h   [NN * 128];   // layer1 output (post-ReLU, 51.2 MB)
__device__ float g_t   [NN * 64];    // h @ W2_l^T (transform-then-aggregate)
__device__ float g_agg2[NN * 64];    // layer2 neighbor sums
__device__ float g_cnt [NN];         // in-degree counts (fp32)

// ---------------------------------------------------------------------------
// Zero all accumulators (grid-stride, float4 stores)
// ---------------------------------------------------------------------------
__global__ void zero_kernel() {
    const int i = blockIdx.x * blockDim.x + threadIdx.x;
    const int stride = gridDim.x * blockDim.x;
    const float4 z = make_float4(0.f, 0.f, 0.f, 0.f);
    for (int j = i; j < NN * 16; j += stride) {
        reinterpret_cast<float4*>(g_agg1)[j] = z;
        reinterpret_cast<float4*>(g_agg2)[j] = z;
    }
    for (int j = i; j < NN / 4; j += stride)
        reinterpret_cast<float4*>(g_cnt)[j] = z;
}

// ---------------------------------------------------------------------------
// Edge scatter: 16 threads per edge, one float4 (4 channels) each.
// LAYER==1: feat = x, agg = g_agg1, lane 0 counts degree.
// LAYER==2: feat = g_t, agg = g_agg2.
// ---------------------------------------------------------------------------
template <int LAYER>
__global__ void __launch_bounds__(256) scatter64_kernel(
    const float* __restrict__ x,
    const int* __restrict__ src,
    const int* __restrict__ dst)
{
    const int idx = blockIdx.x * 256 + threadIdx.x;
    const int e = idx >> 4;
    const int c = idx & 15;
    if (e >= EE) return;

    const int s = __ldg(src + e);
    const int d = __ldg(dst + e);

    const float* feat = (LAYER == 1) ? x : g_t;
    float*       agg  = (LAYER == 1) ? g_agg1 : g_agg2;

    const float4 v = __ldg(
        reinterpret_cast<const float4*>(feat + (size_t)s * 64) + c);
    float* p = agg + (size_t)d * 64 + c * 4;
    asm volatile("red.global.add.v4.f32 [%0], {%1,%2,%3,%4};"
                 :: "l"(p), "f"(v.x), "f"(v.y), "f"(v.z), "f"(v.w)
                 : "memory");

    if (LAYER == 1 && c == 0) {
        float* cp = g_cnt + d;
        asm volatile("red.global.add.f32 [%0], %1;"
                     :: "l"(cp), "f"(1.0f) : "memory");
    }
}

// ---------------------------------------------------------------------------
// Tiled dense kernel. One block = 64 nodes x 128 outputs, K=128.
// Weights staged ONCE per block in shared memory (transposed, padded pitch).
// 256 threads: og = tid>>4 (16 groups of 8 outs), ng = tid&15 (16 groups of
// 4 nodes). Each thread: 8x4 register tile -> 32 FFMA per k-step.
//
// LAYER==1: in = [agg1/cnt | x], W = [W1l | W1r] (rows 128, k 0..63 from l,
//           64..127 from r), +b1l, ReLU -> g_h.
// LAYER==2: in = g_h, W rows 0..63 = W2l -> g_t (no bias),
//           rows 64..127 = W2r -> out (+b2l).
// ---------------------------------------------------------------------------
#define WST_PITCH 132                      // floats per k-row (33 float4)
#define INS_PITCH 68                       // floats per k-row (17 float4)
#define DENSE_SMEM ((128 * WST_PITCH + 128 * INS_PITCH) * 4)   // 102400 B

template <int LAYER>
__global__ void __launch_bounds__(256, 2) dense_kernel(
    const float* __restrict__ x,     // layer1 only
    const float* __restrict__ Wa,    // W1l / W2l
    const float* __restrict__ bias,  // b1l / b2l
    const float* __restrict__ Wb,    // W1r / W2r
    float* __restrict__ out)         // unused / harness out
{
    extern __shared__ float sm[];
    float* Wst = sm;                        // [128][WST_PITCH]
    float* Ins = sm + 128 * WST_PITCH;      // [128][INS_PITCH]

    const int tid = threadIdx.x;
    const int og = tid >> 4;     // 0..15, outs og*8..og*8+7
    const int ng = tid & 15;     // 0..15, nodes n0+ng*4..+3
    const int n0 = blockIdx.x * 64;

    // ---- Stage W transposed: Wst[k][c] -----------------------------------
    const float4* Wa4 = reinterpret_cast<const float4*>(Wa);
    const float4* Wb4 = reinterpret_cast<const float4*>(Wb);
#pragma unroll
    for (int i = 0; i < 16; i++) {
        const int idx = tid + i * 256;      // 4096 float4
        const int c = idx & 127;
        const int kq = idx >> 7;            // float4 index along k
        float4 v;
        if (LAYER == 1) {
            // rows of W1l/W1r are 64 floats = 16 float4
            v = (kq < 16) ? __ldg(Wa4 + c * 16 + kq)
                          : __ldg(Wb4 + c * 16 + (kq - 16));
        } else {
            // rows are 128 floats = 32 float4; c<64 -> W2l, else W2r
            v = (c < 64) ? __ldg(Wa4 + c * 32 + kq)
                         : __ldg(Wb4 + (c - 64) * 32 + kq);
        }
        const int k = kq * 4;
        Wst[(k + 0) * WST_PITCH + c] = v.x;
        Wst[(k + 1) * WST_PITCH + c] = v.y;
        Wst[(k + 2) * WST_PITCH + c] = v.z;
        Wst[(k + 3) * WST_PITCH + c] = v.w;
    }

    // ---- Stage inputs transposed: Ins[k][n_local] ------------------------
    const float4* x4 = reinterpret_cast<const float4*>(x);
    const float4* a4 = reinterpret_cast<const float4*>(g_agg1);
    const float4* h4 = reinterpret_cast<const float4*>(g_h);
#pragma unroll
    for (int i = 0; i < 8; i++) {
        const int idx = tid + i * 256;      // 2048 float4
        const int nl = idx & 63;
        const int kq = idx >> 6;            // 0..31
        int node = n0 + nl;
        if (node >= NN) node = NN - 1;      // clamp (stores are guarded)
        float4 v;
        if (LAYER == 1) {
            if (kq < 16) {
                const float inv = 1.0f / fmaxf(g_cnt[node], 1.0f);
                v = a4[node * 16 + kq];
                v.x *= inv; v.y *= inv; v.z *= inv; v.w *= inv;
            } else {
                v = __ldg(x4 + node * 16 + (kq - 16));
            }
        } else {
            v = h4[node * 32 + kq];
        }
        const int k = kq * 4;
        Ins[(k + 0) * INS_PITCH + nl] = v.x;
        Ins[(k + 1) * INS_PITCH + nl] = v.y;
        Ins[(k + 2) * INS_PITCH + nl] = v.z;
        Ins[(k + 3) * INS_PITCH + nl] = v.w;
    }

    __syncthreads();

    // ---- Register-tiled compute: 8 outs x 4 nodes ------------------------
    float acc[8][4];
#pragma unroll
    for (int a = 0; a < 8; a++)
#pragma unroll
        for (int b = 0; b < 4; b++) acc[a][b] = 0.0f;

    const float4* Wst4 = reinterpret_cast<const float4*>(Wst);
    const float4* Ins4 = reinterpret_cast<const float4*>(Ins);
    const int wbase = og * 2;               // float4 offset of this thread's outs

#pragma unroll 4
    for (int k = 0; k < 128; k++) {
        const float4 w0 = Wst4[k * 33 + wbase];       // outs 0..3 (broadcast)
        const float4 w1 = Wst4[k * 33 + wbase + 1];   // outs 4..7
        const float4 iv = Ins4[k * 17 + ng];          // 4 nodes, conflict-free
        acc[0][0] += w0.x * iv.x; acc[0][1] += w0.x * iv.y; acc[0][2] += w0.x * iv.z; acc[0][3] += w0.x * iv.w;
        acc[1][0] += w0.y * iv.x; acc[1][1] += w0.y * iv.y; acc[1][2] += w0.y * iv.z; acc[1][3] += w0.y * iv.w;
        acc[2][0] += w0.z * iv.x; acc[2][1] += w0.z * iv.y; acc[2][2] += w0.z * iv.z; acc[2][3] += w0.z * iv.w;
        acc[3][0] += w0.w * iv.x; acc[3][1] += w0.w * iv.y; acc[3][2] += w0.w * iv.z; acc[3][3] += w0.w * iv.w;
        acc[4][0] += w1.x * iv.x; acc[4][1] += w1.x * iv.y; acc[4][2] += w1.x * iv.z; acc[4][3] += w1.x * iv.w;
        acc[5][0] += w1.y * iv.x; acc[5][1] += w1.y * iv.y; acc[5][2] += w1.y * iv.z; acc[5][3] += w1.y * iv.w;
        acc[6][0] += w1.z * iv.x; acc[6][1] += w1.z * iv.y; acc[6][2] += w1.z * iv.z; acc[6][3] += w1.z * iv.w;
        acc[7][0] += w1.w * iv.x; acc[7][1] += w1.w * iv.y; acc[7][2] += w1.w * iv.z; acc[7][3] += w1.w * iv.w;
    }

    // ---- Bias / activation / store ---------------------------------------
    const float4* b4 = reinterpret_cast<const float4*>(bias);
    float4 bi0, bi1;
    if (LAYER == 1) {
        bi0 = __ldg(b4 + og * 2);
        bi1 = __ldg(b4 + og * 2 + 1);
    } else {
        if (og >= 8) {                       // right half -> out, biased
            bi0 = __ldg(b4 + (og - 8) * 2);
            bi1 = __ldg(b4 + (og - 8) * 2 + 1);
        } else {
            bi0 = make_float4(0.f, 0.f, 0.f, 0.f);
            bi1 = bi0;
        }
    }

    float4* gh4  = reinterpret_cast<float4*>(g_h);
    float4* gt4  = reinterpret_cast<float4*>(g_t);
    float4* out4 = reinterpret_cast<float4*>(out);

#pragma unroll
    for (int nj = 0; nj < 4; nj++) {
        const int node = n0 + ng * 4 + nj;
        if (node >= NN) continue;
        float4 o0 = make_float4(acc[0][nj] + bi0.x, acc[1][nj] + bi0.y,
                                acc[2][nj] + bi0.z, acc[3][nj] + bi0.w);
        float4 o1 = make_float4(acc[4][nj] + bi1.x, acc[5][nj] + bi1.y,
                                acc[6][nj] + bi1.z, acc[7][nj] + bi1.w);
        if (LAYER == 1) {
            o0.x = fmaxf(o0.x, 0.f); o0.y = fmaxf(o0.y, 0.f);
            o0.z = fmaxf(o0.z, 0.f); o0.w = fmaxf(o0.w, 0.f);
            o1.x = fmaxf(o1.x, 0.f); o1.y = fmaxf(o1.y, 0.f);
            o1.z = fmaxf(o1.z, 0.f); o1.w = fmaxf(o1.w, 0.f);
            gh4[node * 32 + og * 2]     = o0;
            gh4[node * 32 + og * 2 + 1] = o1;
        } else {
            if (og < 8) {                    // c = og*8.. -> g_t
                gt4[node * 16 + og * 2]     = o0;
                gt4[node * 16 + og * 2 + 1] = o1;
            } else {                         // c-64 -> out (+bias done)
                out4[node * 16 + (og - 8) * 2]     = o0;
                out4[node * 16 + (og - 8) * 2 + 1] = o1;
            }
        }
    }
}

// ---------------------------------------------------------------------------
// Finalize: out += agg2 / clip(cnt,1)
// ---------------------------------------------------------------------------
__global__ void __launch_bounds__(256) finalize_kernel(float* __restrict__ out)
{
    const int idx = blockIdx.x * 256 + threadIdx.x;   // one float4 each
    if (idx >= NN * 16) return;
    const int node = idx >> 4;
    const float inv = 1.0f / fmaxf(g_cnt[node], 1.0f);
    const float4 a = reinterpret_cast<const float4*>(g_agg2)[idx];
    float4* o = reinterpret_cast<float4*>(out) + idx;
    float4 v = *o;
    v.x += a.x * inv;
    v.y += a.y * inv;
    v.z += a.z * inv;
    v.w += a.w * inv;
    *o = v;
}

// ---------------------------------------------------------------------------
extern "C" void kernel_launch(void* const* d_in, const int* in_sizes, int n_in,
                              void* d_out, int out_size)
{
    const float* x    = (const float*)d_in[0];
    const int*   ei   = (const int*)  d_in[1];
    const float* W1l  = (const float*)d_in[2];
    const float* b1l  = (const float*)d_in[3];
    const float* W1r  = (const float*)d_in[4];
    const float* W2l  = (const float*)d_in[5];
    const float* b2l  = (const float*)d_in[6];
    const float* W2r  = (const float*)d_in[7];
    float* out = (float*)d_out;

    const int* src = ei;
    const int* dst = ei + EE;

    cudaFuncSetAttribute(dense_kernel<1>,
                         cudaFuncAttributeMaxDynamicSharedMemorySize, DENSE_SMEM);
    cudaFuncSetAttribute(dense_kernel<2>,
                         cudaFuncAttributeMaxDynamicSharedMemorySize, DENSE_SMEM);

    zero_kernel<<<4096, 256>>>();

    // Layer 1 aggregation (+ degree count)
    scatter64_kernel<1><<<(EE * 16) / 256, 256>>>(x, src, dst);

    // Layer 1 dense + ReLU  (h = relu([mean|x] @ Wcat^T + b))
    dense_kernel<1><<<(NN + 63) / 64, 256, DENSE_SMEM>>>(x, W1l, b1l, W1r, out);

    // Layer 2 transforms (t = h@W2l^T ; out = h@W2r^T + b2l)
    dense_kernel<2><<<(NN + 63) / 64, 256, DENSE_SMEM>>>(x, W2l, b2l, W2r, out);

    // Layer 2 aggregation of transformed features
    scatter64_kernel<2><<<(EE * 16) / 256, 256>>>(x, src, dst);

    // out += mean-aggregated transformed neighbors
    finalize_kernel<<<(NN * 16 + 255) / 256, 256>>>(out);
}

// round 11
// speedup vs baseline: 8.8282x; 1.2727x over previous
#include <cuda_runtime.h>

#define NN 100000
#define EE 1600000
// H = 64, hidden = 128, O = 64

// Scratch (device globals — no allocation allowed)
__device__ float g_agg1[NN * 64];    // layer1 neighbor MEANS   (25.6 MB)
__device__ float g_h   [NN * 128];   // layer1 output (post-ReLU, 51.2 MB)
__device__ float g_t   [NN * 64];    // h @ W2_l^T (transform-then-aggregate)
__device__ float g_agg2[NN * 64];    // layer2 neighbor MEANS
// CSR machinery
__device__ int g_deg     [NN];
__device__ int g_cursor  [NN];
__device__ int g_incl    [NN];       // inclusive scan of deg (per 1024-chunk)
__device__ int g_rowstart[NN];       // exclusive prefix (global)
__device__ int g_partial [128];      // per-chunk sums
__device__ int g_poff    [128];      // exclusive scan of partials
__device__ int g_csr     [EE];       // src indices grouped by dst

#define SCAN_BLOCKS ((NN + 1023) / 1024)   // 98

// ---------------------------------------------------------------------------
// Zero the small int arrays (deg, cursor)
// ---------------------------------------------------------------------------
__global__ void zero_small_kernel() {
    const int i = blockIdx.x * blockDim.x + threadIdx.x;
    if (i < NN) { g_deg[i] = 0; g_cursor[i] = 0; }
}

// ---------------------------------------------------------------------------
// Degree histogram
// ---------------------------------------------------------------------------
__global__ void __launch_bounds__(256) hist_kernel(const int* __restrict__ dst) {
    const int e = blockIdx.x * 256 + threadIdx.x;
    if (e < EE) atomicAdd(&g_deg[__ldg(dst + e)], 1);
}

// ---------------------------------------------------------------------------
// Scan phase A: per-1024-chunk inclusive scan + chunk sums
// ---------------------------------------------------------------------------
__global__ void __launch_bounds__(1024) scanA_kernel() {
    __shared__ int s[1024];
    const int t = threadIdx.x;
    const int i = blockIdx.x * 1024 + t;
    int v = (i < NN) ? g_deg[i] : 0;
    s[t] = v;
    __syncthreads();
#pragma unroll
    for (int off = 1; off < 1024; off <<= 1) {
        int add = (t >= off) ? s[t - off] : 0;
        __syncthreads();
        s[t] += add;
        __syncthreads();
    }
    if (i < NN) g_incl[i] = s[t];
    if (t == 1023) g_partial[blockIdx.x] = s[1023];
}

// ---------------------------------------------------------------------------
// Scan phase B: exclusive scan of the (<=128) chunk sums, single block
// ---------------------------------------------------------------------------
__global__ void __launch_bounds__(128) scanB_kernel() {
    __shared__ int s[128];
    const int t = threadIdx.x;
    int own = (t < SCAN_BLOCKS) ? g_partial[t] : 0;
    s[t] = own;
    __syncthreads();
#pragma unroll
    for (int off = 1; off < 128; off <<= 1) {
        int add = (t >= off) ? s[t - off] : 0;
        __syncthreads();
        s[t] += add;
        __syncthreads();
    }
    g_poff[t] = s[t] - own;              // exclusive
}

// ---------------------------------------------------------------------------
// Scan phase C: global exclusive row starts
// ---------------------------------------------------------------------------
__global__ void __launch_bounds__(256) scanC_kernel() {
    const int i = blockIdx.x * 256 + threadIdx.x;
    if (i < NN)
        g_rowstart[i] = g_incl[i] - g_deg[i] + g_poff[i >> 10];
}

// ---------------------------------------------------------------------------
// CSR fill: csr[rowstart[d] + pos] = src
// ---------------------------------------------------------------------------
__global__ void __launch_bounds__(256) fill_kernel(
    const int* __restrict__ src, const int* __restrict__ dst)
{
    const int e = blockIdx.x * 256 + threadIdx.x;
    if (e >= EE) return;
    const int d = __ldg(dst + e);
    const int pos = atomicAdd(&g_cursor[d], 1);
    g_csr[g_rowstart[d] + pos] = __ldg(src + e);
}

// ---------------------------------------------------------------------------
// Gather-aggregate with fused mean: 16 lanes per node, one float4 each.
// LAYER==1: feat = x -> g_agg1.  LAYER==2: feat = g_t -> g_agg2.
// ---------------------------------------------------------------------------
template <int LAYER>
__global__ void __launch_bounds__(256) gather64_kernel(
    const float* __restrict__ feat_in)
{
    const int idx = blockIdx.x * 256 + threadIdx.x;   // NN*16 exactly
    const int node = idx >> 4;
    const int c = idx & 15;

    const float* featp = (LAYER == 1) ? feat_in : g_t;
    const float4* f4 = reinterpret_cast<const float4*>(featp);
    float*       agg = (LAYER == 1) ? g_agg1 : g_agg2;

    const int row = g_rowstart[node];
    const int deg = g_deg[node];

    float4 a0 = make_float4(0.f, 0.f, 0.f, 0.f);
    float4 a1 = make_float4(0.f, 0.f, 0.f, 0.f);
    int i = 0;
    for (; i + 1 < deg; i += 2) {
        const int s0 = __ldg(g_csr + row + i);
        const int s1 = __ldg(g_csr + row + i + 1);
        const float4 v0 = __ldg(f4 + (size_t)s0 * 16 + c);
        const float4 v1 = __ldg(f4 + (size_t)s1 * 16 + c);
        a0.x += v0.x; a0.y += v0.y; a0.z += v0.z; a0.w += v0.w;
        a1.x += v1.x; a1.y += v1.y; a1.z += v1.z; a1.w += v1.w;
    }
    if (i < deg) {
        const int s0 = __ldg(g_csr + row + i);
        const float4 v0 = __ldg(f4 + (size_t)s0 * 16 + c);
        a0.x += v0.x; a0.y += v0.y; a0.z += v0.z; a0.w += v0.w;
    }
    const float inv = 1.0f / (float)(deg > 1 ? deg : 1);
    float4 r;
    r.x = (a0.x + a1.x) * inv;
    r.y = (a0.y + a1.y) * inv;
    r.z = (a0.z + a1.z) * inv;
    r.w = (a0.w + a1.w) * inv;
    reinterpret_cast<float4*>(agg)[idx] = r;
}

// ---------------------------------------------------------------------------
// Tiled dense kernel (agg arrays hold MEANS).
// One block = 64 nodes x 128 outputs, K=128.
// ---------------------------------------------------------------------------
#define WST_PITCH 132                      // floats per k-row (33 float4)
#define INS_PITCH 68                       // floats per k-row (17 float4)
#define DENSE_SMEM ((128 * WST_PITCH + 128 * INS_PITCH) * 4)   // 102400 B

template <int LAYER>
__global__ void __launch_bounds__(256, 2) dense_kernel(
    const float* __restrict__ x,     // layer1 only
    const float* __restrict__ Wa,    // W1l / W2l
    const float* __restrict__ bias,  // b1l / b2l
    const float* __restrict__ Wb,    // W1r / W2r
    float* __restrict__ out)
{
    extern __shared__ float sm[];
    float* Wst = sm;                        // [128][WST_PITCH]
    float* Ins = sm + 128 * WST_PITCH;      // [128][INS_PITCH]

    const int tid = threadIdx.x;
    const int og = tid >> 4;
    const int ng = tid & 15;
    const int n0 = blockIdx.x * 64;

    // ---- Stage W transposed: Wst[k][c] -----------------------------------
    const float4* Wa4 = reinterpret_cast<const float4*>(Wa);
    const float4* Wb4 = reinterpret_cast<const float4*>(Wb);
#pragma unroll
    for (int i = 0; i < 16; i++) {
        const int idx = tid + i * 256;
        const int c = idx & 127;
        const int kq = idx >> 7;
        float4 v;
        if (LAYER == 1) {
            v = (kq < 16) ? __ldg(Wa4 + c * 16 + kq)
                          : __ldg(Wb4 + c * 16 + (kq - 16));
        } else {
            v = (c < 64) ? __ldg(Wa4 + c * 32 + kq)
                         : __ldg(Wb4 + (c - 64) * 32 + kq);
        }
        const int k = kq * 4;
        Wst[(k + 0) * WST_PITCH + c] = v.x;
        Wst[(k + 1) * WST_PITCH + c] = v.y;
        Wst[(k + 2) * WST_PITCH + c] = v.z;
        Wst[(k + 3) * WST_PITCH + c] = v.w;
    }

    // ---- Stage inputs transposed: Ins[k][n_local] ------------------------
    const float4* x4 = reinterpret_cast<const float4*>(x);
    const float4* a4 = reinterpret_cast<const float4*>(g_agg1);
    const float4* h4 = reinterpret_cast<const float4*>(g_h);
#pragma unroll
    for (int i = 0; i < 8; i++) {
        const int idx = tid + i * 256;
        const int nl = idx & 63;
        const int kq = idx >> 6;
        int node = n0 + nl;
        if (node >= NN) node = NN - 1;
        float4 v;
        if (LAYER == 1) {
            if (kq < 16) v = a4[node * 16 + kq];              // mean, pre-divided
            else         v = __ldg(x4 + node * 16 + (kq - 16));
        } else {
            v = h4[node * 32 + kq];
        }
        const int k = kq * 4;
        Ins[(k + 0) * INS_PITCH + nl] = v.x;
        Ins[(k + 1) * INS_PITCH + nl] = v.y;
        Ins[(k + 2) * INS_PITCH + nl] = v.z;
        Ins[(k + 3) * INS_PITCH + nl] = v.w;
    }

    __syncthreads();

    // ---- Register-tiled compute: 8 outs x 4 nodes ------------------------
    float acc[8][4];
#pragma unroll
    for (int a = 0; a < 8; a++)
#pragma unroll
        for (int b = 0; b < 4; b++) acc[a][b] = 0.0f;

    const float4* Wst4 = reinterpret_cast<const float4*>(Wst);
    const float4* Ins4 = reinterpret_cast<const float4*>(Ins);
    const int wbase = og * 2;

#pragma unroll 4
    for (int k = 0; k < 128; k++) {
        const float4 w0 = Wst4[k * 33 + wbase];
        const float4 w1 = Wst4[k * 33 + wbase + 1];
        const float4 iv = Ins4[k * 17 + ng];
        acc[0][0] += w0.x * iv.x; acc[0][1] += w0.x * iv.y; acc[0][2] += w0.x * iv.z; acc[0][3] += w0.x * iv.w;
        acc[1][0] += w0.y * iv.x; acc[1][1] += w0.y * iv.y; acc[1][2] += w0.y * iv.z; acc[1][3] += w0.y * iv.w;
        acc[2][0] += w0.z * iv.x; acc[2][1] += w0.z * iv.y; acc[2][2] += w0.z * iv.z; acc[2][3] += w0.z * iv.w;
        acc[3][0] += w0.w * iv.x; acc[3][1] += w0.w * iv.y; acc[3][2] += w0.w * iv.z; acc[3][3] += w0.w * iv.w;
        acc[4][0] += w1.x * iv.x; acc[4][1] += w1.x * iv.y; acc[4][2] += w1.x * iv.z; acc[4][3] += w1.x * iv.w;
        acc[5][0] += w1.y * iv.x; acc[5][1] += w1.y * iv.y; acc[5][2] += w1.y * iv.z; acc[5][3] += w1.y * iv.w;
        acc[6][0] += w1.z * iv.x; acc[6][1] += w1.z * iv.y; acc[6][2] += w1.z * iv.z; acc[6][3] += w1.z * iv.w;
        acc[7][0] += w1.w * iv.x; acc[7][1] += w1.w * iv.y; acc[7][2] += w1.w * iv.z; acc[7][3] += w1.w * iv.w;
    }

    // ---- Bias / activation / store ---------------------------------------
    const float4* b4 = reinterpret_cast<const float4*>(bias);
    float4 bi0, bi1;
    if (LAYER == 1) {
        bi0 = __ldg(b4 + og * 2);
        bi1 = __ldg(b4 + og * 2 + 1);
    } else {
        if (og >= 8) {
            bi0 = __ldg(b4 + (og - 8) * 2);
            bi1 = __ldg(b4 + (og - 8) * 2 + 1);
        } else {
            bi0 = make_float4(0.f, 0.f, 0.f, 0.f);
            bi1 = bi0;
        }
    }

    float4* gh4  = reinterpret_cast<float4*>(g_h);
    float4* gt4  = reinterpret_cast<float4*>(g_t);
    float4* out4 = reinterpret_cast<float4*>(out);

#pragma unroll
    for (int nj = 0; nj < 4; nj++) {
        const int node = n0 + ng * 4 + nj;
        if (node >= NN) continue;
        float4 o0 = make_float4(acc[0][nj] + bi0.x, acc[1][nj] + bi0.y,
                                acc[2][nj] + bi0.z, acc[3][nj] + bi0.w);
        float4 o1 = make_float4(acc[4][nj] + bi1.x, acc[5][nj] + bi1.y,
                                acc[6][nj] + bi1.z, acc[7][nj] + bi1.w);
        if (LAYER == 1) {
            o0.x = fmaxf(o0.x, 0.f); o0.y = fmaxf(o0.y, 0.f);
            o0.z = fmaxf(o0.z, 0.f); o0.w = fmaxf(o0.w, 0.f);
            o1.x = fmaxf(o1.x, 0.f); o1.y = fmaxf(o1.y, 0.f);
            o1.z = fmaxf(o1.z, 0.f); o1.w = fmaxf(o1.w, 0.f);
            gh4[node * 32 + og * 2]     = o0;
            gh4[node * 32 + og * 2 + 1] = o1;
        } else {
            if (og < 8) {
                gt4[node * 16 + og * 2]     = o0;
                gt4[node * 16 + og * 2 + 1] = o1;
            } else {
                out4[node * 16 + (og - 8) * 2]     = o0;
                out4[node * 16 + (og - 8) * 2 + 1] = o1;
            }
        }
    }
}

// ---------------------------------------------------------------------------
// Finalize: out += agg2 (already a mean)
// ---------------------------------------------------------------------------
__global__ void __launch_bounds__(256) finalize_kernel(float* __restrict__ out)
{
    const int idx = blockIdx.x * 256 + threadIdx.x;   // NN*16 exactly
    const float4 a = reinterpret_cast<const float4*>(g_agg2)[idx];
    float4* o = reinterpret_cast<float4*>(out) + idx;
    float4 v = *o;
    v.x += a.x;
    v.y += a.y;
    v.z += a.z;
    v.w += a.w;
    *o = v;
}

// ---------------------------------------------------------------------------
extern "C" void kernel_launch(void* const* d_in, const int* in_sizes, int n_in,
                              void* d_out, int out_size)
{
    const float* x    = (const float*)d_in[0];
    const int*   ei   = (const int*)  d_in[1];
    const float* W1l  = (const float*)d_in[2];
    const float* b1l  = (const float*)d_in[3];
    const float* W1r  = (const float*)d_in[4];
    const float* W2l  = (const float*)d_in[5];
    const float* b2l  = (const float*)d_in[6];
    const float* W2r  = (const float*)d_in[7];
    float* out = (float*)d_out;

    const int* src = ei;
    const int* dst = ei + EE;

    cudaFuncSetAttribute(dense_kernel<1>,
                         cudaFuncAttributeMaxDynamicSharedMemorySize, DENSE_SMEM);
    cudaFuncSetAttribute(dense_kernel<2>,
                         cudaFuncAttributeMaxDynamicSharedMemorySize, DENSE_SMEM);

    // ---- CSR build (reused by both layers) ----
    zero_small_kernel<<<(NN + 255) / 256, 256>>>();
    hist_kernel<<<EE / 256, 256>>>(dst);
    scanA_kernel<<<SCAN_BLOCKS, 1024>>>();
    scanB_kernel<<<1, 128>>>();
    scanC_kernel<<<(NN + 255) / 256, 256>>>();
    fill_kernel<<<EE / 256, 256>>>(src, dst);

    // ---- Layer 1 ----
    gather64_kernel<1><<<(NN * 16) / 256, 256>>>(x);          // -> g_agg1 (mean)
    dense_kernel<1><<<(NN + 63) / 64, 256, DENSE_SMEM>>>(x, W1l, b1l, W1r, out);

    // ---- Layer 2 (transform-then-aggregate) ----
    dense_kernel<2><<<(NN + 63) / 64, 256, DENSE_SMEM>>>(x, W2l, b2l, W2r, out);
    gather64_kernel<2><<<(NN * 16) / 256, 256>>>(x);          // g_t -> g_agg2 (mean)
    finalize_kernel<<<(NN * 16) / 256, 256>>>(out);
}